// round 4
// baseline (speedup 1.0000x reference)
#include <cuda_runtime.h>
#include <math.h>

// Problem constants
#define NB   32      // batch
#define TT   1024    // T
#define LL   1023    // L = T-1 (after conv slice)
#define SS   1024    // S
#define EE   256     // E
#define HH   256     // H
#define H2   512     // 2H
#define KW   1536    // conv GEMM K = 3*2H

// Scratch (allocation-free rule: __device__ globals)
__device__ float g_x[(size_t)NB * TT * H2];        // (B,T,2H)     67 MB
__device__ float g_y[(size_t)NB * LL * H2];        // (B,L,2H)     67 MB
__device__ float g_dec[(size_t)NB * LL * HH];      // (B,L,H)      33.5 MB
__device__ float g_scores[(size_t)NB * LL * SS];   // (B,L,S)     134 MB

// ---------------------------------------------------------------------------
// GEMM tile config: 64x64 tile, BK=16, 256 threads, 4x4 per thread.
// NT convention: C[m,n] = dot(Arow_m, Brow_n), both K-contiguous.
// ---------------------------------------------------------------------------

// Stage 1: x[b,t,:] = emb[target[t,b]] @ affine_w^T + affine_b
// M = NB*TT = 32768, N = 512, K = 256
__global__ __launch_bounds__(256) void k_embed_affine(
    const int* __restrict__ target, const float* __restrict__ emb,
    const float* __restrict__ aw, const float* __restrict__ ab)
{
    __shared__ float As[16][64];
    __shared__ float Bs[16][64];
    const int M = NB * TT;
    int bm = blockIdx.x * 64, bn = blockIdx.y * 64;
    int tid = threadIdx.x;
    int tx = tid & 15, ty = tid >> 4;
    int lrow = tid >> 2, lk4 = (tid & 3) << 2;

    int arowi = bm + lrow;
    const float* arow = nullptr;
    if (arowi < M) {
        int b = arowi >> 10;        // / TT
        int t = arowi & 1023;       // % TT
        arow = emb + (size_t)target[t * NB + b] * EE;
    }
    const float* brow = aw + (size_t)(bn + lrow) * EE;

    float acc[4][4] = {};
    for (int k0 = 0; k0 < EE; k0 += 16) {
        float4 a4 = arow ? *(const float4*)(arow + k0 + lk4) : make_float4(0.f,0.f,0.f,0.f);
        float4 b4 = *(const float4*)(brow + k0 + lk4);
        As[lk4+0][lrow]=a4.x; As[lk4+1][lrow]=a4.y; As[lk4+2][lrow]=a4.z; As[lk4+3][lrow]=a4.w;
        Bs[lk4+0][lrow]=b4.x; Bs[lk4+1][lrow]=b4.y; Bs[lk4+2][lrow]=b4.z; Bs[lk4+3][lrow]=b4.w;
        __syncthreads();
        #pragma unroll
        for (int k = 0; k < 16; k++) {
            float4 a = *(const float4*)&As[k][ty << 2];
            float4 b = *(const float4*)&Bs[k][tx << 2];
            float av[4] = {a.x,a.y,a.z,a.w};
            float bv[4] = {b.x,b.y,b.z,b.w};
            #pragma unroll
            for (int i = 0; i < 4; i++)
                #pragma unroll
                for (int j = 0; j < 4; j++)
                    acc[i][j] += av[i] * bv[j];
        }
        __syncthreads();
    }
    #pragma unroll
    for (int i = 0; i < 4; i++) {
        int row = bm + (ty << 2) + i;
        if (row >= M) continue;
        #pragma unroll
        for (int j = 0; j < 4; j++) {
            int col = bn + (tx << 2) + j;
            g_x[(size_t)row * H2 + col] = acc[i][j] + ab[col];
        }
    }
}

// Stage 2: conv (as GEMM over K=3*512 with time-gathered A) + bias + relu
// y[b,t,o] = relu(conv_b[o] + sum_{kh,c} x[b,t+kh-2,c] * w[o,kh,c]), t in [0,1023)
// M = NB*LL = 32736, N = 512, K = 1536
__global__ __launch_bounds__(256) void k_conv(
    const float* __restrict__ cw, const float* __restrict__ cb)
{
    __shared__ float As[16][64];
    __shared__ float Bs[16][64];
    const int M = NB * LL;
    int bm = blockIdx.x * 64, bn = blockIdx.y * 64;
    int tid = threadIdx.x;
    int tx = tid & 15, ty = tid >> 4;
    int lrow = tid >> 2, lk4 = (tid & 3) << 2;

    int arowi = bm + lrow;
    bool valid = arowi < M;
    int b = 0, t = 0;
    if (valid) { b = arowi / LL; t = arowi % LL; }
    const float* brow = cw + (size_t)(bn + lrow) * KW;

    float acc[4][4] = {};
    for (int k0 = 0; k0 < KW; k0 += 16) {
        int kh = k0 >> 9;                 // chunk never crosses kh boundary
        int c  = (k0 & 511) + lk4;
        int ts = t + kh - 2;
        float4 a4 = (valid && ts >= 0)
            ? *(const float4*)(g_x + (size_t)(b * TT + ts) * H2 + c)
            : make_float4(0.f,0.f,0.f,0.f);
        float4 b4 = *(const float4*)(brow + k0 + lk4);
        As[lk4+0][lrow]=a4.x; As[lk4+1][lrow]=a4.y; As[lk4+2][lrow]=a4.z; As[lk4+3][lrow]=a4.w;
        Bs[lk4+0][lrow]=b4.x; Bs[lk4+1][lrow]=b4.y; Bs[lk4+2][lrow]=b4.z; Bs[lk4+3][lrow]=b4.w;
        __syncthreads();
        #pragma unroll
        for (int k = 0; k < 16; k++) {
            float4 a = *(const float4*)&As[k][ty << 2];
            float4 b4v = *(const float4*)&Bs[k][tx << 2];
            float av[4] = {a.x,a.y,a.z,a.w};
            float bv[4] = {b4v.x,b4v.y,b4v.z,b4v.w};
            #pragma unroll
            for (int i = 0; i < 4; i++)
                #pragma unroll
                for (int j = 0; j < 4; j++)
                    acc[i][j] += av[i] * bv[j];
        }
        __syncthreads();
    }
    #pragma unroll
    for (int i = 0; i < 4; i++) {
        int row = bm + (ty << 2) + i;
        if (row >= M) continue;
        #pragma unroll
        for (int j = 0; j < 4; j++) {
            int col = bn + (tx << 2) + j;
            g_y[(size_t)row * H2 + col] = fmaxf(acc[i][j] + cb[col], 0.0f);
        }
    }
}

// Stage 3: dec_attn[r,h] = A[r,h] * softmax_h(Bg[r,:]) , A=y[:,:256], Bg=y[:,256:]
__global__ __launch_bounds__(256) void k_gate()
{
    int r = blockIdx.x;
    int h = threadIdx.x;
    const float* yr = g_y + (size_t)r * H2;
    float a = yr[h];
    float g = yr[HH + h];
    __shared__ float sred[8];
    float m = g;
    #pragma unroll
    for (int o = 16; o > 0; o >>= 1) m = fmaxf(m, __shfl_xor_sync(0xffffffffu, m, o));
    if ((h & 31) == 0) sred[h >> 5] = m;
    __syncthreads();
    if (h < 8) {
        float v = sred[h];
        #pragma unroll
        for (int o = 4; o > 0; o >>= 1) v = fmaxf(v, __shfl_xor_sync(0xffu, v, o));
        if (h == 0) sred[0] = v;
    }
    __syncthreads();
    m = sred[0];
    float e = __expf(g - m);
    __syncthreads();
    float s = e;
    #pragma unroll
    for (int o = 16; o > 0; o >>= 1) s += __shfl_xor_sync(0xffffffffu, s, o);
    if ((h & 31) == 0) sred[h >> 5] = s;
    __syncthreads();
    if (h < 8) {
        float v = sred[h];
        #pragma unroll
        for (int o = 4; o > 0; o >>= 1) v += __shfl_xor_sync(0xffu, v, o);
        if (h == 0) sred[0] = v;
    }
    __syncthreads();
    s = sred[0];
    g_dec[(size_t)r * HH + h] = a * (e / s);
}

// Stage 4: d_out = dec_attn @ map_w^T + map_b   (M=32736, N=512, K=256)
__global__ __launch_bounds__(256) void k_dec2(
    const float* __restrict__ mw, const float* __restrict__ mb,
    float* __restrict__ out)
{
    __shared__ float As[16][64];
    __shared__ float Bs[16][64];
    const int M = NB * LL;
    int bm = blockIdx.x * 64, bn = blockIdx.y * 64;
    int tid = threadIdx.x;
    int tx = tid & 15, ty = tid >> 4;
    int lrow = tid >> 2, lk4 = (tid & 3) << 2;

    int arowi = bm + lrow;
    bool valid = arowi < M;
    const float* arow = g_dec + (size_t)arowi * HH;
    const float* brow = mw + (size_t)(bn + lrow) * HH;

    float acc[4][4] = {};
    for (int k0 = 0; k0 < HH; k0 += 16) {
        float4 a4 = valid ? *(const float4*)(arow + k0 + lk4) : make_float4(0.f,0.f,0.f,0.f);
        float4 b4 = *(const float4*)(brow + k0 + lk4);
        As[lk4+0][lrow]=a4.x; As[lk4+1][lrow]=a4.y; As[lk4+2][lrow]=a4.z; As[lk4+3][lrow]=a4.w;
        Bs[lk4+0][lrow]=b4.x; Bs[lk4+1][lrow]=b4.y; Bs[lk4+2][lrow]=b4.z; Bs[lk4+3][lrow]=b4.w;
        __syncthreads();
        #pragma unroll
        for (int k = 0; k < 16; k++) {
            float4 a = *(const float4*)&As[k][ty << 2];
            float4 b = *(const float4*)&Bs[k][tx << 2];
            float av[4] = {a.x,a.y,a.z,a.w};
            float bv[4] = {b.x,b.y,b.z,b.w};
            #pragma unroll
            for (int i = 0; i < 4; i++)
                #pragma unroll
                for (int j = 0; j < 4; j++)
                    acc[i][j] += av[i] * bv[j];
        }
        __syncthreads();
    }
    #pragma unroll
    for (int i = 0; i < 4; i++) {
        int row = bm + (ty << 2) + i;
        if (row >= M) continue;
        #pragma unroll
        for (int j = 0; j < 4; j++) {
            int col = bn + (tx << 2) + j;
            out[(size_t)row * H2 + col] = acc[i][j] + mb[col];
        }
    }
}

// Stage 5: scores[b,l,s] = sum_h dec[b,l,h]*enc[b,s,h]   (batched NT, M=1023,N=1024,K=256)
__global__ __launch_bounds__(256) void k_scores(const float* __restrict__ enc)
{
    __shared__ float As[16][64];
    __shared__ float Bs[16][64];
    int bb = blockIdx.z;
    int bm = blockIdx.x * 64, bn = blockIdx.y * 64;
    int tid = threadIdx.x;
    int tx = tid & 15, ty = tid >> 4;
    int lrow = tid >> 2, lk4 = (tid & 3) << 2;

    int arowi = bm + lrow;
    bool valid = arowi < LL;
    const float* arow = g_dec + (size_t)(bb * LL + arowi) * HH;
    const float* brow = enc + (size_t)(bb * SS + bn + lrow) * HH;

    float acc[4][4] = {};
    for (int k0 = 0; k0 < HH; k0 += 16) {
        float4 a4 = valid ? *(const float4*)(arow + k0 + lk4) : make_float4(0.f,0.f,0.f,0.f);
        float4 b4 = *(const float4*)(brow + k0 + lk4);
        As[lk4+0][lrow]=a4.x; As[lk4+1][lrow]=a4.y; As[lk4+2][lrow]=a4.z; As[lk4+3][lrow]=a4.w;
        Bs[lk4+0][lrow]=b4.x; Bs[lk4+1][lrow]=b4.y; Bs[lk4+2][lrow]=b4.z; Bs[lk4+3][lrow]=b4.w;
        __syncthreads();
        #pragma unroll
        for (int k = 0; k < 16; k++) {
            float4 a = *(const float4*)&As[k][ty << 2];
            float4 b = *(const float4*)&Bs[k][tx << 2];
            float av[4] = {a.x,a.y,a.z,a.w};
            float bv[4] = {b.x,b.y,b.z,b.w};
            #pragma unroll
            for (int i = 0; i < 4; i++)
                #pragma unroll
                for (int j = 0; j < 4; j++)
                    acc[i][j] += av[i] * bv[j];
        }
        __syncthreads();
    }
    #pragma unroll
    for (int i = 0; i < 4; i++) {
        int row = bm + (ty << 2) + i;
        if (row >= LL) continue;
        #pragma unroll
        for (int j = 0; j < 4; j++) {
            int col = bn + (tx << 2) + j;
            g_scores[(size_t)(bb * LL + row) * SS + col] = acc[i][j];
        }
    }
}

// Stage 6: softmax over S=1024 per (b,l) row, in place
__global__ __launch_bounds__(256) void k_softmax_s()
{
    int r = blockIdx.x;
    int t = threadIdx.x;
    float* row = g_scores + (size_t)r * SS;
    float4 v = *(float4*)(row + (t << 2));
    __shared__ float sred[8];
    float m = fmaxf(fmaxf(v.x, v.y), fmaxf(v.z, v.w));
    #pragma unroll
    for (int o = 16; o > 0; o >>= 1) m = fmaxf(m, __shfl_xor_sync(0xffffffffu, m, o));
    if ((t & 31) == 0) sred[t >> 5] = m;
    __syncthreads();
    if (t < 8) {
        float w = sred[t];
        #pragma unroll
        for (int o = 4; o > 0; o >>= 1) w = fmaxf(w, __shfl_xor_sync(0xffu, w, o));
        if (t == 0) sred[0] = w;
    }
    __syncthreads();
    m = sred[0];
    float ex = __expf(v.x - m), ey = __expf(v.y - m);
    float ez = __expf(v.z - m), ew = __expf(v.w - m);
    __syncthreads();
    float s = ex + ey + ez + ew;
    #pragma unroll
    for (int o = 16; o > 0; o >>= 1) s += __shfl_xor_sync(0xffffffffu, s, o);
    if ((t & 31) == 0) sred[t >> 5] = s;
    __syncthreads();
    if (t < 8) {
        float w = sred[t];
        #pragma unroll
        for (int o = 4; o > 0; o >>= 1) w += __shfl_xor_sync(0xffu, w, o);
        if (t == 0) sred[0] = w;
    }
    __syncthreads();
    float inv = 1.0f / sred[0];
    v.x = ex * inv; v.y = ey * inv; v.z = ez * inv; v.w = ew * inv;
    *(float4*)(row + (t << 2)) = v;
}

// Stage 7: d_out += attn @ source_seq_out  (batched NN, M=1023, N=512, K=1024)
__global__ __launch_bounds__(256) void k_attns(
    const float* __restrict__ sso, float* __restrict__ out)
{
    __shared__ float As[16][64];
    __shared__ float Bs[16][64];
    int bb = blockIdx.z;
    int bm = blockIdx.x * 64, bn = blockIdx.y * 64;
    int tid = threadIdx.x;
    int tx = tid & 15, ty = tid >> 4;
    int lrow = tid >> 2, lk4 = (tid & 3) << 2;     // A-load (transposed store)
    int kr = tid >> 4, n0 = (tid & 15) << 2;       // B-load (direct store)

    int arowi = bm + lrow;
    bool valid = arowi < LL;
    const float* arow = g_scores + (size_t)(bb * LL + arowi) * SS;
    const float* bbase = sso + (size_t)bb * SS * H2;

    float acc[4][4] = {};
    for (int k0 = 0; k0 < SS; k0 += 16) {
        float4 a4 = valid ? *(const float4*)(arow + k0 + lk4) : make_float4(0.f,0.f,0.f,0.f);
        float4 b4 = *(const float4*)(bbase + (size_t)(k0 + kr) * H2 + bn + n0);
        As[lk4+0][lrow]=a4.x; As[lk4+1][lrow]=a4.y; As[lk4+2][lrow]=a4.z; As[lk4+3][lrow]=a4.w;
        *(float4*)&Bs[kr][n0] = b4;
        __syncthreads();
        #pragma unroll
        for (int k = 0; k < 16; k++) {
            float4 a = *(const float4*)&As[k][ty << 2];
            float4 b = *(const float4*)&Bs[k][tx << 2];
            float av[4] = {a.x,a.y,a.z,a.w};
            float bv[4] = {b.x,b.y,b.z,b.w};
            #pragma unroll
            for (int i = 0; i < 4; i++)
                #pragma unroll
                for (int j = 0; j < 4; j++)
                    acc[i][j] += av[i] * bv[j];
        }
        __syncthreads();
    }
    #pragma unroll
    for (int i = 0; i < 4; i++) {
        int row = bm + (ty << 2) + i;
        if (row >= LL) continue;
        #pragma unroll
        for (int j = 0; j < 4; j++) {
            int col = bn + (tx << 2) + j;
            out[(size_t)(bb * LL + row) * H2 + col] += acc[i][j];
        }
    }
}

// ---------------------------------------------------------------------------
extern "C" void kernel_launch(void* const* d_in, const int* in_sizes, int n_in,
                              void* d_out, int out_size)
{
    // metadata order: source, target, enc_attn, source_seq_out, emb,
    //                 affine_w, affine_b, conv_w, conv_b, map_w, map_b
    const int*   target = (const int*)  d_in[1];
    const float* enc    = (const float*)d_in[2];
    const float* sso    = (const float*)d_in[3];
    const float* emb    = (const float*)d_in[4];
    const float* aw     = (const float*)d_in[5];
    const float* ab     = (const float*)d_in[6];
    const float* cw     = (const float*)d_in[7];
    const float* cb     = (const float*)d_in[8];
    const float* mw     = (const float*)d_in[9];
    const float* mb     = (const float*)d_in[10];
    float* out = (float*)d_out;

    k_embed_affine<<<dim3(512, 8), 256>>>(target, emb, aw, ab);          // (B,T,2H)
    k_conv<<<dim3(512, 8), 256>>>(cw, cb);                               // (B,L,2H)
    k_gate<<<NB * LL, 256>>>();                                          // (B,L,H)
    k_dec2<<<dim3(512, 8), 256>>>(mw, mb, out);                          // writes d_out
    k_scores<<<dim3(16, 16, NB), 256>>>(enc);                            // (B,L,S)
    k_softmax_s<<<NB * LL, 256>>>();
    k_attns<<<dim3(16, 8, NB), 256>>>(sso, out);                         // += into d_out
}

// round 6
// speedup vs baseline: 1.0114x; 1.0114x over previous
#include <cuda_runtime.h>
#include <math.h>

// Problem constants
#define NB   32      // batch
#define TT   1024    // T
#define LL   1023    // L = T-1 (after conv slice)
#define SS   1024    // S
#define EE   256     // E
#define HH   256     // H
#define H2   512     // 2H
#define KW   1536    // conv GEMM K = 3*2H

// Scratch (allocation-free rule: __device__ globals)
__device__ float g_x[(size_t)NB * TT * H2];        // (B,T,2H)     67 MB
__device__ float g_y[(size_t)NB * LL * H2];        // (B,L,2H)     67 MB
__device__ float g_dec[(size_t)NB * LL * HH];      // (B,L,H)      33.5 MB
__device__ float g_scores[(size_t)NB * LL * SS];   // (B,L,S)     134 MB

// ---------------------------------------------------------------------------
// Packed fp32x2 helpers (sm_103a FFMA2: 2x FFMA-3reg throughput; only
// reachable via PTX fma.rn.f32x2 — ptxas never auto-fuses).
// ---------------------------------------------------------------------------
typedef unsigned long long u64t;

__device__ __forceinline__ u64t bcast2(float x) {
    u64t r;
    asm("mov.b64 %0, {%1, %1};" : "=l"(r) : "f"(x));
    return r;
}
__device__ __forceinline__ void ffma2(u64t& d, u64t a, u64t b) {
    asm("fma.rn.f32x2 %0, %1, %2, %3;" : "=l"(d) : "l"(a), "l"(b), "l"(d));
}
__device__ __forceinline__ float2 unpack2(u64t v) {
    float lo, hi;
    asm("mov.b64 {%0, %1}, %2;" : "=f"(lo), "=f"(hi) : "l"(v));
    return make_float2(lo, hi);
}

// Inner 4x4 micro-tile update using packed pairs along the column (j) dim.
// acc[i][0] holds C(i, 4*tx+0 .. +1), acc[i][1] holds C(i, 4*tx+2 .. +3).
#define MICRO_FFMA2(As, Bs, acc, ty, tx)                                    \
    _Pragma("unroll")                                                       \
    for (int k = 0; k < 16; k++) {                                          \
        float4 a = *(const float4*)&As[k][(ty) << 2];                       \
        ulonglong2 bp = *(const ulonglong2*)&Bs[k][(tx) << 2];              \
        u64t a0 = bcast2(a.x), a1 = bcast2(a.y);                            \
        u64t a2 = bcast2(a.z), a3 = bcast2(a.w);                            \
        ffma2(acc[0][0], a0, bp.x); ffma2(acc[0][1], a0, bp.y);             \
        ffma2(acc[1][0], a1, bp.x); ffma2(acc[1][1], a1, bp.y);             \
        ffma2(acc[2][0], a2, bp.x); ffma2(acc[2][1], a2, bp.y);             \
        ffma2(acc[3][0], a3, bp.x); ffma2(acc[3][1], a3, bp.y);             \
    }

// ---------------------------------------------------------------------------
// GEMM tile config: 64x64 tile, BK=16, 256 threads, 4x4 per thread.
// NT convention: C[m,n] = dot(Arow_m, Brow_n), both K-contiguous.
// ---------------------------------------------------------------------------

// Stage 1: x[b,t,:] = emb[target[t,b]] @ affine_w^T + affine_b
// M = NB*TT = 32768, N = 512, K = 256
__global__ __launch_bounds__(256) void k_embed_affine(
    const int* __restrict__ target, const float* __restrict__ emb,
    const float* __restrict__ aw, const float* __restrict__ ab)
{
    __shared__ float As[16][64];
    __shared__ float Bs[16][64];
    const int M = NB * TT;
    int bm = blockIdx.x * 64, bn = blockIdx.y * 64;
    int tid = threadIdx.x;
    int tx = tid & 15, ty = tid >> 4;
    int lrow = tid >> 2, lk4 = (tid & 3) << 2;

    int arowi = bm + lrow;
    const float* arow = nullptr;
    if (arowi < M) {
        int b = arowi >> 10;        // / TT
        int t = arowi & 1023;       // % TT
        arow = emb + (size_t)target[t * NB + b] * EE;
    }
    const float* brow = aw + (size_t)(bn + lrow) * EE;

    u64t acc[4][2] = {};
    for (int k0 = 0; k0 < EE; k0 += 16) {
        float4 a4 = arow ? *(const float4*)(arow + k0 + lk4) : make_float4(0.f,0.f,0.f,0.f);
        float4 b4 = *(const float4*)(brow + k0 + lk4);
        As[lk4+0][lrow]=a4.x; As[lk4+1][lrow]=a4.y; As[lk4+2][lrow]=a4.z; As[lk4+3][lrow]=a4.w;
        Bs[lk4+0][lrow]=b4.x; Bs[lk4+1][lrow]=b4.y; Bs[lk4+2][lrow]=b4.z; Bs[lk4+3][lrow]=b4.w;
        __syncthreads();
        MICRO_FFMA2(As, Bs, acc, ty, tx)
        __syncthreads();
    }
    #pragma unroll
    for (int i = 0; i < 4; i++) {
        int row = bm + (ty << 2) + i;
        if (row >= M) continue;
        #pragma unroll
        for (int j2 = 0; j2 < 2; j2++) {
            float2 v = unpack2(acc[i][j2]);
            int col = bn + (tx << 2) + (j2 << 1);
            g_x[(size_t)row * H2 + col + 0] = v.x + ab[col + 0];
            g_x[(size_t)row * H2 + col + 1] = v.y + ab[col + 1];
        }
    }
}

// Stage 2: conv (as GEMM over K=3*512 with time-gathered A) + bias + relu
// M = NB*LL = 32736, N = 512, K = 1536
__global__ __launch_bounds__(256) void k_conv(
    const float* __restrict__ cw, const float* __restrict__ cb)
{
    __shared__ float As[16][64];
    __shared__ float Bs[16][64];
    const int M = NB * LL;
    int bm = blockIdx.x * 64, bn = blockIdx.y * 64;
    int tid = threadIdx.x;
    int tx = tid & 15, ty = tid >> 4;
    int lrow = tid >> 2, lk4 = (tid & 3) << 2;

    int arowi = bm + lrow;
    bool valid = arowi < M;
    int b = 0, t = 0;
    if (valid) { b = arowi / LL; t = arowi % LL; }
    const float* brow = cw + (size_t)(bn + lrow) * KW;

    u64t acc[4][2] = {};
    for (int k0 = 0; k0 < KW; k0 += 16) {
        int kh = k0 >> 9;                 // chunk never crosses kh boundary
        int c  = (k0 & 511) + lk4;
        int ts = t + kh - 2;
        float4 a4 = (valid && ts >= 0)
            ? *(const float4*)(g_x + (size_t)(b * TT + ts) * H2 + c)
            : make_float4(0.f,0.f,0.f,0.f);
        float4 b4 = *(const float4*)(brow + k0 + lk4);
        As[lk4+0][lrow]=a4.x; As[lk4+1][lrow]=a4.y; As[lk4+2][lrow]=a4.z; As[lk4+3][lrow]=a4.w;
        Bs[lk4+0][lrow]=b4.x; Bs[lk4+1][lrow]=b4.y; Bs[lk4+2][lrow]=b4.z; Bs[lk4+3][lrow]=b4.w;
        __syncthreads();
        MICRO_FFMA2(As, Bs, acc, ty, tx)
        __syncthreads();
    }
    #pragma unroll
    for (int i = 0; i < 4; i++) {
        int row = bm + (ty << 2) + i;
        if (row >= M) continue;
        #pragma unroll
        for (int j2 = 0; j2 < 2; j2++) {
            float2 v = unpack2(acc[i][j2]);
            int col = bn + (tx << 2) + (j2 << 1);
            g_y[(size_t)row * H2 + col + 0] = fmaxf(v.x + cb[col + 0], 0.0f);
            g_y[(size_t)row * H2 + col + 1] = fmaxf(v.y + cb[col + 1], 0.0f);
        }
    }
}

// Stage 3: dec_attn[r,h] = A[r,h] * softmax_h(Bg[r,:]) , A=y[:,:256], Bg=y[:,256:]
__global__ __launch_bounds__(256) void k_gate()
{
    int r = blockIdx.x;
    int h = threadIdx.x;
    const float* yr = g_y + (size_t)r * H2;
    float a = yr[h];
    float g = yr[HH + h];
    __shared__ float sred[8];
    float m = g;
    #pragma unroll
    for (int o = 16; o > 0; o >>= 1) m = fmaxf(m, __shfl_xor_sync(0xffffffffu, m, o));
    if ((h & 31) == 0) sred[h >> 5] = m;
    __syncthreads();
    if (h < 8) {
        float v = sred[h];
        #pragma unroll
        for (int o = 4; o > 0; o >>= 1) v = fmaxf(v, __shfl_xor_sync(0xffu, v, o));
        if (h == 0) sred[0] = v;
    }
    __syncthreads();
    m = sred[0];
    float e = __expf(g - m);
    __syncthreads();
    float s = e;
    #pragma unroll
    for (int o = 16; o > 0; o >>= 1) s += __shfl_xor_sync(0xffffffffu, s, o);
    if ((h & 31) == 0) sred[h >> 5] = s;
    __syncthreads();
    if (h < 8) {
        float v = sred[h];
        #pragma unroll
        for (int o = 4; o > 0; o >>= 1) v += __shfl_xor_sync(0xffu, v, o);
        if (h == 0) sred[0] = v;
    }
    __syncthreads();
    s = sred[0];
    g_dec[(size_t)r * HH + h] = a * (e / s);
}

// Stage 4: d_out = dec_attn @ map_w^T + map_b   (M=32736, N=512, K=256)
__global__ __launch_bounds__(256) void k_dec2(
    const float* __restrict__ mw, const float* __restrict__ mb,
    float* __restrict__ out)
{
    __shared__ float As[16][64];
    __shared__ float Bs[16][64];
    const int M = NB * LL;
    int bm = blockIdx.x * 64, bn = blockIdx.y * 64;
    int tid = threadIdx.x;
    int tx = tid & 15, ty = tid >> 4;
    int lrow = tid >> 2, lk4 = (tid & 3) << 2;

    int arowi = bm + lrow;
    bool valid = arowi < M;
    const float* arow = g_dec + (size_t)arowi * HH;
    const float* brow = mw + (size_t)(bn + lrow) * HH;

    u64t acc[4][2] = {};
    for (int k0 = 0; k0 < HH; k0 += 16) {
        float4 a4 = valid ? *(const float4*)(arow + k0 + lk4) : make_float4(0.f,0.f,0.f,0.f);
        float4 b4 = *(const float4*)(brow + k0 + lk4);
        As[lk4+0][lrow]=a4.x; As[lk4+1][lrow]=a4.y; As[lk4+2][lrow]=a4.z; As[lk4+3][lrow]=a4.w;
        Bs[lk4+0][lrow]=b4.x; Bs[lk4+1][lrow]=b4.y; Bs[lk4+2][lrow]=b4.z; Bs[lk4+3][lrow]=b4.w;
        __syncthreads();
        MICRO_FFMA2(As, Bs, acc, ty, tx)
        __syncthreads();
    }
    #pragma unroll
    for (int i = 0; i < 4; i++) {
        int row = bm + (ty << 2) + i;
        if (row >= M) continue;
        #pragma unroll
        for (int j2 = 0; j2 < 2; j2++) {
            float2 v = unpack2(acc[i][j2]);
            int col = bn + (tx << 2) + (j2 << 1);
            out[(size_t)row * H2 + col + 0] = v.x + mb[col + 0];
            out[(size_t)row * H2 + col + 1] = v.y + mb[col + 1];
        }
    }
}

// Stage 5: scores[b,l,s] = sum_h dec[b,l,h]*enc[b,s,h]   (batched NT, M=1023,N=1024,K=256)
__global__ __launch_bounds__(256) void k_scores(const float* __restrict__ enc)
{
    __shared__ float As[16][64];
    __shared__ float Bs[16][64];
    int bb = blockIdx.z;
    int bm = blockIdx.x * 64, bn = blockIdx.y * 64;
    int tid = threadIdx.x;
    int tx = tid & 15, ty = tid >> 4;
    int lrow = tid >> 2, lk4 = (tid & 3) << 2;

    int arowi = bm + lrow;
    bool valid = arowi < LL;
    const float* arow = g_dec + (size_t)(bb * LL + arowi) * HH;
    const float* brow = enc + (size_t)(bb * SS + bn + lrow) * HH;

    u64t acc[4][2] = {};
    for (int k0 = 0; k0 < HH; k0 += 16) {
        float4 a4 = valid ? *(const float4*)(arow + k0 + lk4) : make_float4(0.f,0.f,0.f,0.f);
        float4 b4 = *(const float4*)(brow + k0 + lk4);
        As[lk4+0][lrow]=a4.x; As[lk4+1][lrow]=a4.y; As[lk4+2][lrow]=a4.z; As[lk4+3][lrow]=a4.w;
        Bs[lk4+0][lrow]=b4.x; Bs[lk4+1][lrow]=b4.y; Bs[lk4+2][lrow]=b4.z; Bs[lk4+3][lrow]=b4.w;
        __syncthreads();
        MICRO_FFMA2(As, Bs, acc, ty, tx)
        __syncthreads();
    }
    #pragma unroll
    for (int i = 0; i < 4; i++) {
        int row = bm + (ty << 2) + i;
        if (row >= LL) continue;
        #pragma unroll
        for (int j2 = 0; j2 < 2; j2++) {
            float2 v = unpack2(acc[i][j2]);
            int col = bn + (tx << 2) + (j2 << 1);
            g_scores[(size_t)(bb * LL + row) * SS + col + 0] = v.x;
            g_scores[(size_t)(bb * LL + row) * SS + col + 1] = v.y;
        }
    }
}

// Stage 6: softmax over S=1024 per (b,l) row, in place
__global__ __launch_bounds__(256) void k_softmax_s()
{
    int r = blockIdx.x;
    int t = threadIdx.x;
    float* row = g_scores + (size_t)r * SS;
    float4 v = *(float4*)(row + (t << 2));
    __shared__ float sred[8];
    float m = fmaxf(fmaxf(v.x, v.y), fmaxf(v.z, v.w));
    #pragma unroll
    for (int o = 16; o > 0; o >>= 1) m = fmaxf(m, __shfl_xor_sync(0xffffffffu, m, o));
    if ((t & 31) == 0) sred[t >> 5] = m;
    __syncthreads();
    if (t < 8) {
        float w = sred[t];
        #pragma unroll
        for (int o = 4; o > 0; o >>= 1) w = fmaxf(w, __shfl_xor_sync(0xffu, w, o));
        if (t == 0) sred[0] = w;
    }
    __syncthreads();
    m = sred[0];
    float ex = __expf(v.x - m), ey = __expf(v.y - m);
    float ez = __expf(v.z - m), ew = __expf(v.w - m);
    __syncthreads();
    float s = ex + ey + ez + ew;
    #pragma unroll
    for (int o = 16; o > 0; o >>= 1) s += __shfl_xor_sync(0xffffffffu, s, o);
    if ((t & 31) == 0) sred[t >> 5] = s;
    __syncthreads();
    if (t < 8) {
        float w = sred[t];
        #pragma unroll
        for (int o = 4; o > 0; o >>= 1) w += __shfl_xor_sync(0xffu, w, o);
        if (t == 0) sred[0] = w;
    }
    __syncthreads();
    float inv = 1.0f / sred[0];
    v.x = ex * inv; v.y = ey * inv; v.z = ez * inv; v.w = ew * inv;
    *(float4*)(row + (t << 2)) = v;
}

// Stage 7: d_out += attn @ source_seq_out  (batched NN, M=1023, N=512, K=1024)
__global__ __launch_bounds__(256) void k_attns(
    const float* __restrict__ sso, float* __restrict__ out)
{
    __shared__ float As[16][64];
    __shared__ float Bs[16][64];
    int bb = blockIdx.z;
    int bm = blockIdx.x * 64, bn = blockIdx.y * 64;
    int tid = threadIdx.x;
    int tx = tid & 15, ty = tid >> 4;
    int lrow = tid >> 2, lk4 = (tid & 3) << 2;     // A-load (transposed store)
    int kr = tid >> 4, n0 = (tid & 15) << 2;       // B-load (direct store)

    int arowi = bm + lrow;
    bool valid = arowi < LL;
    const float* arow = g_scores + (size_t)(bb * LL + arowi) * SS;
    const float* bbase = sso + (size_t)bb * SS * H2;

    u64t acc[4][2] = {};
    for (int k0 = 0; k0 < SS; k0 += 16) {
        float4 a4 = valid ? *(const float4*)(arow + k0 + lk4) : make_float4(0.f,0.f,0.f,0.f);
        float4 b4 = *(const float4*)(bbase + (size_t)(k0 + kr) * H2 + bn + n0);
        As[lk4+0][lrow]=a4.x; As[lk4+1][lrow]=a4.y; As[lk4+2][lrow]=a4.z; As[lk4+3][lrow]=a4.w;
        *(float4*)&Bs[kr][n0] = b4;
        __syncthreads();
        MICRO_FFMA2(As, Bs, acc, ty, tx)
        __syncthreads();
    }
    #pragma unroll
    for (int i = 0; i < 4; i++) {
        int row = bm + (ty << 2) + i;
        if (row >= LL) continue;
        #pragma unroll
        for (int j2 = 0; j2 < 2; j2++) {
            float2 v = unpack2(acc[i][j2]);
            int col = bn + (tx << 2) + (j2 << 1);
            out[(size_t)(bb * LL + row) * H2 + col + 0] += v.x;
            out[(size_t)(bb * LL + row) * H2 + col + 1] += v.y;
        }
    }
}

// ---------------------------------------------------------------------------
extern "C" void kernel_launch(void* const* d_in, const int* in_sizes, int n_in,
                              void* d_out, int out_size)
{
    // metadata order: source, target, enc_attn, source_seq_out, emb,
    //                 affine_w, affine_b, conv_w, conv_b, map_w, map_b
    const int*   target = (const int*)  d_in[1];
    const float* enc    = (const float*)d_in[2];
    const float* sso    = (const float*)d_in[3];
    const float* emb    = (const float*)d_in[4];
    const float* aw     = (const float*)d_in[5];
    const float* ab     = (const float*)d_in[6];
    const float* cw     = (const float*)d_in[7];
    const float* cb     = (const float*)d_in[8];
    const float* mw     = (const float*)d_in[9];
    const float* mb     = (const float*)d_in[10];
    float* out = (float*)d_out;

    k_embed_affine<<<dim3(512, 8), 256>>>(target, emb, aw, ab);          // (B,T,2H)
    k_conv<<<dim3(512, 8), 256>>>(cw, cb);                               // (B,L,2H)
    k_gate<<<NB * LL, 256>>>();                                          // (B,L,H)
    k_dec2<<<dim3(512, 8), 256>>>(mw, mb, out);                          // writes d_out
    k_scores<<<dim3(16, 16, NB), 256>>>(enc);                            // (B,L,S)
    k_softmax_s<<<NB * LL, 256>>>();
    k_attns<<<dim3(16, 8, NB), 256>>>(sso, out);                         // += into d_out
}

// round 9
// speedup vs baseline: 1.5803x; 1.5625x over previous
#include <cuda_runtime.h>
#include <math.h>

// Problem constants
#define NB   32      // batch
#define TT   1024    // T
#define LL   1023    // L = T-1 (after conv slice)
#define SS   1024    // S
#define EE   256     // E
#define HH   256     // H
#define H2   512     // 2H
#define KWC  768     // fused conv GEMM K = 3*E

#define MCV  (NB * LL)   // 32736 rows for conv/dec2 GEMMs

// Scratch (allocation-free rule: __device__ globals)
__device__ float g_y[(size_t)NB * LL * H2];        // (B,L,2H)     67 MB
__device__ float g_dec[(size_t)NB * LL * HH];      // (B,L,H)      33.5 MB
__device__ float g_scores[(size_t)NB * LL * SS];   // (B,L,S)     134 MB
__device__ float g_C[3 * H2 * EE];                 // fused conv weights 1.5 MB
__device__ float g_biasK[3 * H2];                  // fused affine-bias-through-conv

// ---------------------------------------------------------------------------
// Packed fp32x2 helpers (sm_103a FFMA2 via PTX fma.rn.f32x2)
// ---------------------------------------------------------------------------
typedef unsigned long long u64t;

__device__ __forceinline__ u64t bcast2(float x) {
    u64t r;
    asm("mov.b64 %0, {%1, %1};" : "=l"(r) : "f"(x));
    return r;
}
__device__ __forceinline__ void ffma2(u64t& d, u64t a, u64t b) {
    asm("fma.rn.f32x2 %0, %1, %2, %3;" : "=l"(d) : "l"(a), "l"(b), "l"(d));
}
__device__ __forceinline__ float2 unpack2(u64t v) {
    float lo, hi;
    asm("mov.b64 {%0, %1}, %2;" : "=f"(lo), "=f"(hi) : "l"(v));
    return make_float2(lo, hi);
}

// ---------------------------------------------------------------------------
// 128x128x16 tile, 256 threads, 8x8 per-thread micro-tile (FFMA2 pairs on n).
// acc[i][0..3] = C(row ty*8+i, cols tx*8 + {0,1 | 2,3 | 4,5 | 6,7})
// ---------------------------------------------------------------------------
#define BKK 16

__device__ __forceinline__ void micro_compute(
    const float (*As)[128], const float (*Bs)[128],
    u64t acc[8][4], int ty8, int tx8)
{
    #pragma unroll
    for (int k = 0; k < BKK; k++) {
        float4 a0 = *(const float4*)&As[k][ty8];
        float4 a1 = *(const float4*)&As[k][ty8 + 4];
        ulonglong2 b0 = *(const ulonglong2*)&Bs[k][tx8];
        ulonglong2 b1 = *(const ulonglong2*)&Bs[k][tx8 + 4];
        u64t a[8];
        a[0] = bcast2(a0.x); a[1] = bcast2(a0.y); a[2] = bcast2(a0.z); a[3] = bcast2(a0.w);
        a[4] = bcast2(a1.x); a[5] = bcast2(a1.y); a[6] = bcast2(a1.z); a[7] = bcast2(a1.w);
        #pragma unroll
        for (int i = 0; i < 8; i++) {
            ffma2(acc[i][0], a[i], b0.x);
            ffma2(acc[i][1], a[i], b0.y);
            ffma2(acc[i][2], a[i], b1.x);
            ffma2(acc[i][3], a[i], b1.y);
        }
    }
}

// transposed (k-major) smem store of one 8-wide K chunk for row r
__device__ __forceinline__ void sts_kmajor(float (*S)[128], int r, int kb,
                                           float4 v0, float4 v1)
{
    S[kb+0][r] = v0.x; S[kb+1][r] = v0.y; S[kb+2][r] = v0.z; S[kb+3][r] = v0.w;
    S[kb+4][r] = v1.x; S[kb+5][r] = v1.y; S[kb+6][r] = v1.z; S[kb+7][r] = v1.w;
}

__device__ __forceinline__ float4 ldg4z(const float* p) {
    return p ? *(const float4*)p : make_float4(0.f, 0.f, 0.f, 0.f);
}

// ---------------------------------------------------------------------------
// Prep A: fused conv weights C[kh,o,e] = sum_c conv_w[o,0,kh,c] * affine_w[c,e]
// GEMM M=1536 (kh,o), N=256 (e), K=512 (c).  A: NT rows, B: NN (aw e-contig).
// ---------------------------------------------------------------------------
__global__ __launch_bounds__(256, 2) void k_prep_C(
    const float* __restrict__ cw, const float* __restrict__ aw)
{
    __shared__ float As[BKK][128];
    __shared__ float Bs[BKK][128];
    int bm = blockIdx.x * 128, bn = blockIdx.y * 128;
    int tid = threadIdx.x;
    int tx8 = (tid & 15) << 3, ty8 = (tid >> 4) << 3;
    int rA = tid >> 1, kbA = (tid & 1) << 3;        // A loader
    int krB = tid >> 4, n0B = (tid & 15) << 3;      // B loader (NN)

    int m = bm + rA;
    int kh = m >> 9, o = m & 511;
    const float* arow = cw + (size_t)o * 1536 + kh * 512;

    u64t acc[8][4] = {};
    float4 a0, a1, b0, b1;
    // prologue load k0 = 0
    a0 = *(const float4*)(arow + kbA);
    a1 = *(const float4*)(arow + kbA + 4);
    b0 = *(const float4*)(aw + (size_t)krB * EE + bn + n0B);
    b1 = *(const float4*)(aw + (size_t)krB * EE + bn + n0B + 4);
    for (int k0 = 0; k0 < 512; k0 += BKK) {
        sts_kmajor(As, rA, kbA, a0, a1);
        *(float4*)&Bs[krB][n0B] = b0;
        *(float4*)&Bs[krB][n0B + 4] = b1;
        __syncthreads();
        int kn = k0 + BKK;
        if (kn < 512) {
            a0 = *(const float4*)(arow + kn + kbA);
            a1 = *(const float4*)(arow + kn + kbA + 4);
            b0 = *(const float4*)(aw + (size_t)(kn + krB) * EE + bn + n0B);
            b1 = *(const float4*)(aw + (size_t)(kn + krB) * EE + bn + n0B + 4);
        }
        micro_compute(As, Bs, acc, ty8, tx8);
        __syncthreads();
    }
    #pragma unroll
    for (int i = 0; i < 8; i++) {
        int row = bm + ty8 + i;
        #pragma unroll
        for (int j2 = 0; j2 < 4; j2++) {
            float2 v = unpack2(acc[i][j2]);
            int col = bn + tx8 + (j2 << 1);
            g_C[(size_t)row * EE + col + 0] = v.x;
            g_C[(size_t)row * EE + col + 1] = v.y;
        }
    }
}

// biasK[kh*512+o] = sum_c conv_w[o,0,kh,c] * ab[c]
__global__ void k_prep_bias(const float* __restrict__ cw, const float* __restrict__ ab)
{
    int m = blockIdx.x * 256 + threadIdx.x;   // 0..1535
    int kh = m >> 9, o = m & 511;
    const float* w = cw + (size_t)o * 1536 + kh * 512;
    float s = 0.f;
    for (int c = 0; c < 512; c++) s += w[c] * ab[c];
    g_biasK[m] = s;
}

// ---------------------------------------------------------------------------
// Fused embed+affine+conv: y[b,t,o] = relu( sum_kh emb[target[t+kh-2,b]] . C[kh,o,:]
//                                           + cb[o] + sum_{valid kh} biasK[kh,o] )
// GEMM M=32736, N=512, K=768 (3 chunks of 256, A row switches per chunk)
// ---------------------------------------------------------------------------
__global__ __launch_bounds__(256, 2) void k_conv_emb(
    const int* __restrict__ target, const float* __restrict__ emb,
    const float* __restrict__ cb)
{
    __shared__ float As[BKK][128];
    __shared__ float Bs[BKK][128];
    int bm = blockIdx.x * 128, bn = blockIdx.y * 128;
    int tid = threadIdx.x;
    int tx8 = (tid & 15) << 3, ty8 = (tid >> 4) << 3;
    int rA = tid >> 1, kbA = (tid & 1) << 3;

    int arowi = bm + rA;
    bool valid = arowi < MCV;
    int b = 0, t = 0;
    if (valid) { b = arowi / LL; t = arowi % LL; }
    const float* p[3];
    #pragma unroll
    for (int kh = 0; kh < 3; kh++) {
        int ts = t + kh - 2;
        p[kh] = (valid && ts >= 0) ? emb + (size_t)target[ts * NB + b] * EE : nullptr;
    }

    u64t acc[8][4] = {};
    float4 a0, a1, b0, b1;
    {   // k0 = 0 (kh=0)
        const float* src = p[0];
        a0 = ldg4z(src ? src + kbA : nullptr);
        a1 = ldg4z(src ? src + kbA + 4 : nullptr);
        const float* br = g_C + (size_t)(bn + rA) * EE + kbA;   // kh=0 block of C
        b0 = *(const float4*)br;
        b1 = *(const float4*)(br + 4);
    }
    for (int k0 = 0; k0 < KWC; k0 += BKK) {
        sts_kmajor(As, rA, kbA, a0, a1);
        sts_kmajor(Bs, rA, kbA, b0, b1);
        __syncthreads();
        int kn = k0 + BKK;
        if (kn < KWC) {
            int kh = kn >> 8;
            int c = (kn & 255) + kbA;
            const float* src = p[kh];
            a0 = ldg4z(src ? src + c : nullptr);
            a1 = ldg4z(src ? src + c + 4 : nullptr);
            const float* br = g_C + (size_t)(kh * H2 + bn + rA) * EE + (kn & 255) + kbA;
            b0 = *(const float4*)br;
            b1 = *(const float4*)(br + 4);
        }
        micro_compute(As, Bs, acc, ty8, tx8);
        __syncthreads();
    }
    #pragma unroll
    for (int i = 0; i < 8; i++) {
        int row = bm + ty8 + i;
        if (row >= MCV) continue;
        int tE = row % LL;
        #pragma unroll
        for (int j2 = 0; j2 < 4; j2++) {
            float2 v = unpack2(acc[i][j2]);
            int col = bn + tx8 + (j2 << 1);
            #pragma unroll
            for (int u = 0; u < 2; u++) {
                int cc = col + u;
                float bias = cb[cc] + g_biasK[2 * H2 + cc];
                if (tE >= 1) bias += g_biasK[1 * H2 + cc];
                if (tE >= 2) bias += g_biasK[cc];
                float val = (u == 0 ? v.x : v.y) + bias;
                g_y[(size_t)row * H2 + cc] = fmaxf(val, 0.0f);
            }
        }
    }
}

// ---------------------------------------------------------------------------
// Gate: dec_attn[r,h] = A[r,h] * softmax_h(Bg[r,:])
// ---------------------------------------------------------------------------
__global__ __launch_bounds__(256) void k_gate()
{
    int r = blockIdx.x;
    int h = threadIdx.x;
    const float* yr = g_y + (size_t)r * H2;
    float a = yr[h];
    float g = yr[HH + h];
    __shared__ float sred[8];
    float m = g;
    #pragma unroll
    for (int o = 16; o > 0; o >>= 1) m = fmaxf(m, __shfl_xor_sync(0xffffffffu, m, o));
    if ((h & 31) == 0) sred[h >> 5] = m;
    __syncthreads();
    if (h < 8) {
        float v = sred[h];
        #pragma unroll
        for (int o = 4; o > 0; o >>= 1) v = fmaxf(v, __shfl_xor_sync(0xffu, v, o));
        if (h == 0) sred[0] = v;
    }
    __syncthreads();
    m = sred[0];
    float e = __expf(g - m);
    __syncthreads();
    float s = e;
    #pragma unroll
    for (int o = 16; o > 0; o >>= 1) s += __shfl_xor_sync(0xffffffffu, s, o);
    if ((h & 31) == 0) sred[h >> 5] = s;
    __syncthreads();
    if (h < 8) {
        float v = sred[h];
        #pragma unroll
        for (int o = 4; o > 0; o >>= 1) v += __shfl_xor_sync(0xffu, v, o);
        if (h == 0) sred[0] = v;
    }
    __syncthreads();
    s = sred[0];
    g_dec[(size_t)r * HH + h] = a * (e / s);
}

// ---------------------------------------------------------------------------
// Stage 4: d_out = dec_attn @ map_w^T + map_b   (M=32736, N=512, K=256, NT)
// ---------------------------------------------------------------------------
__global__ __launch_bounds__(256, 2) void k_dec2(
    const float* __restrict__ mw, const float* __restrict__ mb,
    float* __restrict__ out)
{
    __shared__ float As[BKK][128];
    __shared__ float Bs[BKK][128];
    int bm = blockIdx.x * 128, bn = blockIdx.y * 128;
    int tid = threadIdx.x;
    int tx8 = (tid & 15) << 3, ty8 = (tid >> 4) << 3;
    int rA = tid >> 1, kbA = (tid & 1) << 3;

    int arowi = bm + rA;
    bool valid = arowi < MCV;
    const float* arow = valid ? g_dec + (size_t)arowi * HH : nullptr;
    const float* brow = mw + (size_t)(bn + rA) * HH;

    u64t acc[8][4] = {};
    float4 a0, a1, b0, b1;
    a0 = ldg4z(arow ? arow + kbA : nullptr);
    a1 = ldg4z(arow ? arow + kbA + 4 : nullptr);
    b0 = *(const float4*)(brow + kbA);
    b1 = *(const float4*)(brow + kbA + 4);
    for (int k0 = 0; k0 < HH; k0 += BKK) {
        sts_kmajor(As, rA, kbA, a0, a1);
        sts_kmajor(Bs, rA, kbA, b0, b1);
        __syncthreads();
        int kn = k0 + BKK;
        if (kn < HH) {
            a0 = ldg4z(arow ? arow + kn + kbA : nullptr);
            a1 = ldg4z(arow ? arow + kn + kbA + 4 : nullptr);
            b0 = *(const float4*)(brow + kn + kbA);
            b1 = *(const float4*)(brow + kn + kbA + 4);
        }
        micro_compute(As, Bs, acc, ty8, tx8);
        __syncthreads();
    }
    #pragma unroll
    for (int i = 0; i < 8; i++) {
        int row = bm + ty8 + i;
        if (row >= MCV) continue;
        #pragma unroll
        for (int j2 = 0; j2 < 4; j2++) {
            float2 v = unpack2(acc[i][j2]);
            int col = bn + tx8 + (j2 << 1);
            out[(size_t)row * H2 + col + 0] = v.x + mb[col + 0];
            out[(size_t)row * H2 + col + 1] = v.y + mb[col + 1];
        }
    }
}

// ---------------------------------------------------------------------------
// Stage 5: scores[b,l,s] = dec[b,l,:] . enc[b,s,:]  (batched NT, M=1023,N=1024,K=256)
// ---------------------------------------------------------------------------
__global__ __launch_bounds__(256, 2) void k_scores(const float* __restrict__ enc)
{
    __shared__ float As[BKK][128];
    __shared__ float Bs[BKK][128];
    int bb = blockIdx.z;
    int bm = blockIdx.x * 128, bn = blockIdx.y * 128;
    int tid = threadIdx.x;
    int tx8 = (tid & 15) << 3, ty8 = (tid >> 4) << 3;
    int rA = tid >> 1, kbA = (tid & 1) << 3;

    int arowi = bm + rA;
    bool valid = arowi < LL;
    const float* arow = valid ? g_dec + (size_t)(bb * LL + arowi) * HH : nullptr;
    const float* brow = enc + (size_t)(bb * SS + bn + rA) * HH;

    u64t acc[8][4] = {};
    float4 a0, a1, b0, b1;
    a0 = ldg4z(arow ? arow + kbA : nullptr);
    a1 = ldg4z(arow ? arow + kbA + 4 : nullptr);
    b0 = *(const float4*)(brow + kbA);
    b1 = *(const float4*)(brow + kbA + 4);
    for (int k0 = 0; k0 < HH; k0 += BKK) {
        sts_kmajor(As, rA, kbA, a0, a1);
        sts_kmajor(Bs, rA, kbA, b0, b1);
        __syncthreads();
        int kn = k0 + BKK;
        if (kn < HH) {
            a0 = ldg4z(arow ? arow + kn + kbA : nullptr);
            a1 = ldg4z(arow ? arow + kn + kbA + 4 : nullptr);
            b0 = *(const float4*)(brow + kn + kbA);
            b1 = *(const float4*)(brow + kn + kbA + 4);
        }
        micro_compute(As, Bs, acc, ty8, tx8);
        __syncthreads();
    }
    #pragma unroll
    for (int i = 0; i < 8; i++) {
        int row = bm + ty8 + i;
        if (row >= LL) continue;
        #pragma unroll
        for (int j2 = 0; j2 < 4; j2++) {
            float2 v = unpack2(acc[i][j2]);
            int col = bn + tx8 + (j2 << 1);
            g_scores[(size_t)(bb * LL + row) * SS + col + 0] = v.x;
            g_scores[(size_t)(bb * LL + row) * SS + col + 1] = v.y;
        }
    }
}

// ---------------------------------------------------------------------------
// Stage 6: softmax over S=1024 per (b,l) row, in place
// ---------------------------------------------------------------------------
__global__ __launch_bounds__(256) void k_softmax_s()
{
    int r = blockIdx.x;
    int t = threadIdx.x;
    float* row = g_scores + (size_t)r * SS;
    float4 v = *(float4*)(row + (t << 2));
    __shared__ float sred[8];
    float m = fmaxf(fmaxf(v.x, v.y), fmaxf(v.z, v.w));
    #pragma unroll
    for (int o = 16; o > 0; o >>= 1) m = fmaxf(m, __shfl_xor_sync(0xffffffffu, m, o));
    if ((t & 31) == 0) sred[t >> 5] = m;
    __syncthreads();
    if (t < 8) {
        float w = sred[t];
        #pragma unroll
        for (int o = 4; o > 0; o >>= 1) w = fmaxf(w, __shfl_xor_sync(0xffu, w, o));
        if (t == 0) sred[0] = w;
    }
    __syncthreads();
    m = sred[0];
    float ex = __expf(v.x - m), ey = __expf(v.y - m);
    float ez = __expf(v.z - m), ew = __expf(v.w - m);
    __syncthreads();
    float s = ex + ey + ez + ew;
    #pragma unroll
    for (int o = 16; o > 0; o >>= 1) s += __shfl_xor_sync(0xffffffffu, s, o);
    if ((t & 31) == 0) sred[t >> 5] = s;
    __syncthreads();
    if (t < 8) {
        float w = sred[t];
        #pragma unroll
        for (int o = 4; o > 0; o >>= 1) w += __shfl_xor_sync(0xffu, w, o);
        if (t == 0) sred[0] = w;
    }
    __syncthreads();
    float inv = 1.0f / sred[0];
    v.x = ex * inv; v.y = ey * inv; v.z = ez * inv; v.w = ew * inv;
    *(float4*)(row + (t << 2)) = v;
}

// ---------------------------------------------------------------------------
// Stage 7: d_out += attn @ source_seq_out  (batched NN, M=1023, N=512, K=1024)
// ---------------------------------------------------------------------------
__global__ __launch_bounds__(256, 2) void k_attns(
    const float* __restrict__ sso, float* __restrict__ out)
{
    __shared__ float As[BKK][128];
    __shared__ float Bs[BKK][128];
    int bb = blockIdx.z;
    int bm = blockIdx.x * 128, bn = blockIdx.y * 128;
    int tid = threadIdx.x;
    int tx8 = (tid & 15) << 3, ty8 = (tid >> 4) << 3;
    int rA = tid >> 1, kbA = (tid & 1) << 3;        // A loader (NT, transpose)
    int krB = tid >> 4, n0B = (tid & 15) << 3;      // B loader (NN, direct)

    int arowi = bm + rA;
    bool valid = arowi < LL;
    const float* arow = valid ? g_scores + (size_t)(bb * LL + arowi) * SS : nullptr;
    const float* bbase = sso + (size_t)bb * SS * H2;

    u64t acc[8][4] = {};
    float4 a0, a1, b0, b1;
    a0 = ldg4z(arow ? arow + kbA : nullptr);
    a1 = ldg4z(arow ? arow + kbA + 4 : nullptr);
    b0 = *(const float4*)(bbase + (size_t)krB * H2 + bn + n0B);
    b1 = *(const float4*)(bbase + (size_t)krB * H2 + bn + n0B + 4);
    for (int k0 = 0; k0 < SS; k0 += BKK) {
        sts_kmajor(As, rA, kbA, a0, a1);
        *(float4*)&Bs[krB][n0B] = b0;
        *(float4*)&Bs[krB][n0B + 4] = b1;
        __syncthreads();
        int kn = k0 + BKK;
        if (kn < SS) {
            a0 = ldg4z(arow ? arow + kn + kbA : nullptr);
            a1 = ldg4z(arow ? arow + kn + kbA + 4 : nullptr);
            b0 = *(const float4*)(bbase + (size_t)(kn + krB) * H2 + bn + n0B);
            b1 = *(const float4*)(bbase + (size_t)(kn + krB) * H2 + bn + n0B + 4);
        }
        micro_compute(As, Bs, acc, ty8, tx8);
        __syncthreads();
    }
    #pragma unroll
    for (int i = 0; i < 8; i++) {
        int row = bm + ty8 + i;
        if (row >= LL) continue;
        #pragma unroll
        for (int j2 = 0; j2 < 4; j2++) {
            float2 v = unpack2(acc[i][j2]);
            int col = bn + tx8 + (j2 << 1);
            out[(size_t)(bb * LL + row) * H2 + col + 0] += v.x;
            out[(size_t)(bb * LL + row) * H2 + col + 1] += v.y;
        }
    }
}

// ---------------------------------------------------------------------------
extern "C" void kernel_launch(void* const* d_in, const int* in_sizes, int n_in,
                              void* d_out, int out_size)
{
    // metadata order: source, target, enc_attn, source_seq_out, emb,
    //                 affine_w, affine_b, conv_w, conv_b, map_w, map_b
    const int*   target = (const int*)  d_in[1];
    const float* enc    = (const float*)d_in[2];
    const float* sso    = (const float*)d_in[3];
    const float* emb    = (const float*)d_in[4];
    const float* aw     = (const float*)d_in[5];
    const float* ab     = (const float*)d_in[6];
    const float* cw     = (const float*)d_in[7];
    const float* cb     = (const float*)d_in[8];
    const float* mw     = (const float*)d_in[9];
    const float* mb     = (const float*)d_in[10];
    float* out = (float*)d_out;

    k_prep_C<<<dim3(12, 2), 256>>>(cw, aw);          // fused weights (3,512,256)
    k_prep_bias<<<6, 256>>>(cw, ab);                 // fused affine bias
    k_conv_emb<<<dim3(256, 4), 256>>>(target, emb, cb);  // (B,L,2H)
    k_gate<<<NB * LL, 256>>>();                      // (B,L,H)
    k_dec2<<<dim3(256, 4), 256>>>(mw, mb, out);      // writes d_out
    k_scores<<<dim3(8, 8, NB), 256>>>(enc);          // (B,L,S)
    k_softmax_s<<<NB * LL, 256>>>();
    k_attns<<<dim3(8, 4, NB), 256>>>(sso, out);      // += into d_out
}

// round 17
// speedup vs baseline: 1.5837x; 1.0021x over previous
#include <cuda_runtime.h>
#include <math.h>
#include <stdint.h>

// Problem constants
#define NB   32      // batch
#define TT   1024    // T
#define LL   1023    // L = T-1 (after conv slice)
#define SS   1024    // S
#define EE   256     // E
#define HH   256     // H
#define H2   512     // 2H
#define KWC  768     // fused conv GEMM K = 3*E

#define MCV  (NB * LL)   // 32736 rows

// Scratch (allocation-free rule: __device__ globals)
__device__ float g_y[(size_t)NB * LL * H2];        // (B,L,2H)
__device__ float g_dec[(size_t)NB * LL * HH];      // (B,L,H)
__device__ float g_scores[(size_t)NB * LL * SS];   // (B,L,S)
__device__ float g_C[3 * H2 * EE];                 // fused conv weights
__device__ float g_biasK[3 * H2];                  // fused affine bias

// ---------------------------------------------------------------------------
// Packed fp32x2 helpers (sm_103a FFMA2 via PTX fma.rn.f32x2)
// ---------------------------------------------------------------------------
typedef unsigned long long u64t;

__device__ __forceinline__ u64t bcast2(float x) {
    u64t r;
    asm("mov.b64 %0, {%1, %1};" : "=l"(r) : "f"(x));
    return r;
}
__device__ __forceinline__ void ffma2(u64t& d, u64t a, u64t b) {
    asm("fma.rn.f32x2 %0, %1, %2, %3;" : "=l"(d) : "l"(a), "l"(b), "l"(d));
}
__device__ __forceinline__ float2 unpack2(u64t v) {
    float lo, hi;
    asm("mov.b64 {%0, %1}, %2;" : "=f"(lo), "=f"(hi) : "l"(v));
    return make_float2(lo, hi);
}

#define BKK 16

__device__ __forceinline__ void micro_compute(
    const float (*As)[128], const float (*Bs)[128],
    u64t acc[8][4], int ty8, int tx8)
{
    #pragma unroll
    for (int k = 0; k < BKK; k++) {
        float4 a0 = *(const float4*)&As[k][ty8];
        float4 a1 = *(const float4*)&As[k][ty8 + 4];
        ulonglong2 b0 = *(const ulonglong2*)&Bs[k][tx8];
        ulonglong2 b1 = *(const ulonglong2*)&Bs[k][tx8 + 4];
        u64t a[8];
        a[0] = bcast2(a0.x); a[1] = bcast2(a0.y); a[2] = bcast2(a0.z); a[3] = bcast2(a0.w);
        a[4] = bcast2(a1.x); a[5] = bcast2(a1.y); a[6] = bcast2(a1.z); a[7] = bcast2(a1.w);
        #pragma unroll
        for (int i = 0; i < 8; i++) {
            ffma2(acc[i][0], a[i], b0.x);
            ffma2(acc[i][1], a[i], b0.y);
            ffma2(acc[i][2], a[i], b1.x);
            ffma2(acc[i][3], a[i], b1.y);
        }
    }
}

__device__ __forceinline__ void sts_kmajor(float (*S)[128], int r, int kb,
                                           float4 v0, float4 v1)
{
    S[kb+0][r] = v0.x; S[kb+1][r] = v0.y; S[kb+2][r] = v0.z; S[kb+3][r] = v0.w;
    S[kb+4][r] = v1.x; S[kb+5][r] = v1.y; S[kb+6][r] = v1.z; S[kb+7][r] = v1.w;
}

__device__ __forceinline__ float4 ldg4z(const float* p) {
    return p ? *(const float4*)p : make_float4(0.f, 0.f, 0.f, 0.f);
}

// ---------------------------------------------------------------------------
// Prep: fused conv weights C[kh,o,e] = sum_c conv_w[o,0,kh,c] * affine_w[c,e]
// (small; single-buffered)
// ---------------------------------------------------------------------------
__global__ __launch_bounds__(256, 2) void k_prep_C(
    const float* __restrict__ cw, const float* __restrict__ aw)
{
    __shared__ float As[BKK][128];
    __shared__ float Bs[BKK][128];
    int bm = blockIdx.x * 128, bn = blockIdx.y * 128;
    int tid = threadIdx.x;
    int tx8 = (tid & 15) << 3, ty8 = (tid >> 4) << 3;
    int rA = tid >> 1, kbA = (tid & 1) << 3;
    int krB = tid >> 4, n0B = (tid & 15) << 3;

    int m = bm + rA;
    int kh = m >> 9, o = m & 511;
    const float* arow = cw + (size_t)o * 1536 + kh * 512;

    u64t acc[8][4] = {};
    float4 a0, a1, b0, b1;
    a0 = *(const float4*)(arow + kbA);
    a1 = *(const float4*)(arow + kbA + 4);
    b0 = *(const float4*)(aw + (size_t)krB * EE + bn + n0B);
    b1 = *(const float4*)(aw + (size_t)krB * EE + bn + n0B + 4);
    for (int k0 = 0; k0 < 512; k0 += BKK) {
        sts_kmajor(As, rA, kbA, a0, a1);
        *(float4*)&Bs[krB][n0B] = b0;
        *(float4*)&Bs[krB][n0B + 4] = b1;
        __syncthreads();
        int kn = k0 + BKK;
        if (kn < 512) {
            a0 = *(const float4*)(arow + kn + kbA);
            a1 = *(const float4*)(arow + kn + kbA + 4);
            b0 = *(const float4*)(aw + (size_t)(kn + krB) * EE + bn + n0B);
            b1 = *(const float4*)(aw + (size_t)(kn + krB) * EE + bn + n0B + 4);
        }
        micro_compute(As, Bs, acc, ty8, tx8);
        __syncthreads();
    }
    #pragma unroll
    for (int i = 0; i < 8; i++) {
        int row = bm + ty8 + i;
        #pragma unroll
        for (int j2 = 0; j2 < 4; j2++) {
            float2 v = unpack2(acc[i][j2]);
            int col = bn + tx8 + (j2 << 1);
            g_C[(size_t)row * EE + col + 0] = v.x;
            g_C[(size_t)row * EE + col + 1] = v.y;
        }
    }
}

__global__ void k_prep_bias(const float* __restrict__ cw, const float* __restrict__ ab)
{
    int m = blockIdx.x * 256 + threadIdx.x;
    int kh = m >> 9, o = m & 511;
    const float* w = cw + (size_t)o * 1536 + kh * 512;
    float s = 0.f;
    for (int c = 0; c < 512; c++) s += w[c] * ab[c];
    g_biasK[m] = s;
}

// ---------------------------------------------------------------------------
// Fused embed+affine+conv (ping-pong double-buffered)
// y[b,t,o] = relu( sum_kh emb[target[t+kh-2,b]] . C[kh,o,:] + fused biases )
// GEMM M=32736, N=512, K=768
// ---------------------------------------------------------------------------
__global__ __launch_bounds__(256, 2) void k_conv_emb(
    const int* __restrict__ target, const float* __restrict__ emb,
    const float* __restrict__ cb)
{
    __shared__ float As[2][BKK][128];
    __shared__ float Bs[2][BKK][128];
    int bm = blockIdx.x * 128, bn = blockIdx.y * 128;
    int tid = threadIdx.x;
    int tx8 = (tid & 15) << 3, ty8 = (tid >> 4) << 3;
    int rA = tid >> 1, kbA = (tid & 1) << 3;

    int arowi = bm + rA;
    bool valid = arowi < MCV;
    int b = 0, t = 0;
    if (valid) { b = arowi / LL; t = arowi % LL; }
    const float* p3[3];
    #pragma unroll
    for (int kh = 0; kh < 3; kh++) {
        int ts = t + kh - 2;
        p3[kh] = (valid && ts >= 0) ? emb + (size_t)target[ts * NB + b] * EE : nullptr;
    }

    u64t acc[8][4] = {};
    float4 a0, a1, b0, b1;
    {   // chunk 0 (kh=0)
        const float* src = p3[0];
        a0 = ldg4z(src ? src + kbA : nullptr);
        a1 = ldg4z(src ? src + kbA + 4 : nullptr);
        const float* br = g_C + (size_t)(bn + rA) * EE + kbA;
        b0 = *(const float4*)br;
        b1 = *(const float4*)(br + 4);
    }
    sts_kmajor(As[0], rA, kbA, a0, a1);
    sts_kmajor(Bs[0], rA, kbA, b0, b1);
    __syncthreads();

    int p = 0;
    for (int k0 = 0; k0 < KWC; k0 += BKK) {
        int kn = k0 + BKK;
        if (kn < KWC) {
            int kh = kn >> 8;
            int c = (kn & 255) + kbA;
            const float* src = p3[kh];
            a0 = ldg4z(src ? src + c : nullptr);
            a1 = ldg4z(src ? src + c + 4 : nullptr);
            const float* br = g_C + (size_t)(kh * H2 + bn + rA) * EE + (kn & 255) + kbA;
            b0 = *(const float4*)br;
            b1 = *(const float4*)(br + 4);
        }
        micro_compute(As[p], Bs[p], acc, ty8, tx8);
        if (kn < KWC) {
            sts_kmajor(As[p ^ 1], rA, kbA, a0, a1);
            sts_kmajor(Bs[p ^ 1], rA, kbA, b0, b1);
            __syncthreads();
        }
        p ^= 1;
    }
    #pragma unroll
    for (int i = 0; i < 8; i++) {
        int row = bm + ty8 + i;
        if (row >= MCV) continue;
        int tE = row % LL;
        #pragma unroll
        for (int j2 = 0; j2 < 4; j2++) {
            float2 v = unpack2(acc[i][j2]);
            int col = bn + tx8 + (j2 << 1);
            #pragma unroll
            for (int u = 0; u < 2; u++) {
                int cc = col + u;
                float bias = cb[cc] + g_biasK[2 * H2 + cc];
                if (tE >= 1) bias += g_biasK[1 * H2 + cc];
                if (tE >= 2) bias += g_biasK[cc];
                float val = (u == 0 ? v.x : v.y) + bias;
                g_y[(size_t)row * H2 + cc] = fmaxf(val, 0.0f);
            }
        }
    }
}

// ---------------------------------------------------------------------------
// Gate: dec_attn[r,h] = A[r,h] * softmax_h(Bg[r,:])
// ---------------------------------------------------------------------------
__global__ __launch_bounds__(256) void k_gate()
{
    int r = blockIdx.x;
    int h = threadIdx.x;
    const float* yr = g_y + (size_t)r * H2;
    float a = yr[h];
    float g = yr[HH + h];
    __shared__ float sred[8];
    float m = g;
    #pragma unroll
    for (int o = 16; o > 0; o >>= 1) m = fmaxf(m, __shfl_xor_sync(0xffffffffu, m, o));
    if ((h & 31) == 0) sred[h >> 5] = m;
    __syncthreads();
    if (h < 8) {
        float v = sred[h];
        #pragma unroll
        for (int o = 4; o > 0; o >>= 1) v = fmaxf(v, __shfl_xor_sync(0xffu, v, o));
        if (h == 0) sred[0] = v;
    }
    __syncthreads();
    m = sred[0];
    float e = __expf(g - m);
    __syncthreads();
    float s = e;
    #pragma unroll
    for (int o = 16; o > 0; o >>= 1) s += __shfl_xor_sync(0xffffffffu, s, o);
    if ((h & 31) == 0) sred[h >> 5] = s;
    __syncthreads();
    if (h < 8) {
        float v = sred[h];
        #pragma unroll
        for (int o = 4; o > 0; o >>= 1) v += __shfl_xor_sync(0xffu, v, o);
        if (h == 0) sred[0] = v;
    }
    __syncthreads();
    s = sred[0];
    g_dec[(size_t)r * HH + h] = a * (e / s);
}

// ---------------------------------------------------------------------------
// Stage 4: d_out = dec_attn @ map_w^T + map_b  (M=32736, N=512, K=256; ping-pong)
// ---------------------------------------------------------------------------
__global__ __launch_bounds__(256, 2) void k_dec2(
    const float* __restrict__ mw, const float* __restrict__ mb,
    float* __restrict__ out)
{
    __shared__ float As[2][BKK][128];
    __shared__ float Bs[2][BKK][128];
    int bm = blockIdx.x * 128, bn = blockIdx.y * 128;
    int tid = threadIdx.x;
    int tx8 = (tid & 15) << 3, ty8 = (tid >> 4) << 3;
    int rA = tid >> 1, kbA = (tid & 1) << 3;

    int arowi = bm + rA;
    bool valid = arowi < MCV;
    const float* arow = valid ? g_dec + (size_t)arowi * HH : nullptr;
    const float* brow = mw + (size_t)(bn + rA) * HH;

    u64t acc[8][4] = {};
    float4 a0, a1, b0, b1;
    a0 = ldg4z(arow ? arow + kbA : nullptr);
    a1 = ldg4z(arow ? arow + kbA + 4 : nullptr);
    b0 = *(const float4*)(brow + kbA);
    b1 = *(const float4*)(brow + kbA + 4);
    sts_kmajor(As[0], rA, kbA, a0, a1);
    sts_kmajor(Bs[0], rA, kbA, b0, b1);
    __syncthreads();

    int p = 0;
    for (int k0 = 0; k0 < HH; k0 += BKK) {
        int kn = k0 + BKK;
        if (kn < HH) {
            a0 = ldg4z(arow ? arow + kn + kbA : nullptr);
            a1 = ldg4z(arow ? arow + kn + kbA + 4 : nullptr);
            b0 = *(const float4*)(brow + kn + kbA);
            b1 = *(const float4*)(brow + kn + kbA + 4);
        }
        micro_compute(As[p], Bs[p], acc, ty8, tx8);
        if (kn < HH) {
            sts_kmajor(As[p ^ 1], rA, kbA, a0, a1);
            sts_kmajor(Bs[p ^ 1], rA, kbA, b0, b1);
            __syncthreads();
        }
        p ^= 1;
    }
    #pragma unroll
    for (int i = 0; i < 8; i++) {
        int row = bm + ty8 + i;
        if (row >= MCV) continue;
        #pragma unroll
        for (int j2 = 0; j2 < 4; j2++) {
            float2 v = unpack2(acc[i][j2]);
            int col = bn + tx8 + (j2 << 1);
            out[(size_t)row * H2 + col + 0] = v.x + mb[col + 0];
            out[(size_t)row * H2 + col + 1] = v.y + mb[col + 1];
        }
    }
}

// ---------------------------------------------------------------------------
// Stage 5: scores[b,l,s] = dec[b,l,:] . enc[b,s,:]  (batched NT; ping-pong)
// ---------------------------------------------------------------------------
__global__ __launch_bounds__(256, 2) void k_scores(const float* __restrict__ enc)
{
    __shared__ float As[2][BKK][128];
    __shared__ float Bs[2][BKK][128];
    int bb = blockIdx.z;
    int bm = blockIdx.x * 128, bn = blockIdx.y * 128;
    int tid = threadIdx.x;
    int tx8 = (tid & 15) << 3, ty8 = (tid >> 4) << 3;
    int rA = tid >> 1, kbA = (tid & 1) << 3;

    int arowi = bm + rA;
    bool valid = arowi < LL;
    const float* arow = valid ? g_dec + (size_t)(bb * LL + arowi) * HH : nullptr;
    const float* brow = enc + (size_t)(bb * SS + bn + rA) * HH;

    u64t acc[8][4] = {};
    float4 a0, a1, b0, b1;
    a0 = ldg4z(arow ? arow + kbA : nullptr);
    a1 = ldg4z(arow ? arow + kbA + 4 : nullptr);
    b0 = *(const float4*)(brow + kbA);
    b1 = *(const float4*)(brow + kbA + 4);
    sts_kmajor(As[0], rA, kbA, a0, a1);
    sts_kmajor(Bs[0], rA, kbA, b0, b1);
    __syncthreads();

    int p = 0;
    for (int k0 = 0; k0 < HH; k0 += BKK) {
        int kn = k0 + BKK;
        if (kn < HH) {
            a0 = ldg4z(arow ? arow + kn + kbA : nullptr);
            a1 = ldg4z(arow ? arow + kn + kbA + 4 : nullptr);
            b0 = *(const float4*)(brow + kn + kbA);
            b1 = *(const float4*)(brow + kn + kbA + 4);
        }
        micro_compute(As[p], Bs[p], acc, ty8, tx8);
        if (kn < HH) {
            sts_kmajor(As[p ^ 1], rA, kbA, a0, a1);
            sts_kmajor(Bs[p ^ 1], rA, kbA, b0, b1);
            __syncthreads();
        }
        p ^= 1;
    }
    #pragma unroll
    for (int i = 0; i < 8; i++) {
        int row = bm + ty8 + i;
        if (row >= LL) continue;
        #pragma unroll
        for (int j2 = 0; j2 < 4; j2++) {
            float2 v = unpack2(acc[i][j2]);
            int col = bn + tx8 + (j2 << 1);
            g_scores[(size_t)(bb * LL + row) * SS + col + 0] = v.x;
            g_scores[(size_t)(bb * LL + row) * SS + col + 1] = v.y;
        }
    }
}

// ---------------------------------------------------------------------------
// Stage 6: softmax over S=1024 per (b,l) row, in place
// ---------------------------------------------------------------------------
__global__ __launch_bounds__(256) void k_softmax_s()
{
    int r = blockIdx.x;
    int t = threadIdx.x;
    float* row = g_scores + (size_t)r * SS;
    float4 v = *(float4*)(row + (t << 2));
    __shared__ float sred[8];
    float m = fmaxf(fmaxf(v.x, v.y), fmaxf(v.z, v.w));
    #pragma unroll
    for (int o = 16; o > 0; o >>= 1) m = fmaxf(m, __shfl_xor_sync(0xffffffffu, m, o));
    if ((t & 31) == 0) sred[t >> 5] = m;
    __syncthreads();
    if (t < 8) {
        float w = sred[t];
        #pragma unroll
        for (int o = 4; o > 0; o >>= 1) w = fmaxf(w, __shfl_xor_sync(0xffu, w, o));
        if (t == 0) sred[0] = w;
    }
    __syncthreads();
    m = sred[0];
    float ex = __expf(v.x - m), ey = __expf(v.y - m);
    float ez = __expf(v.z - m), ew = __expf(v.w - m);
    __syncthreads();
    float s = ex + ey + ez + ew;
    #pragma unroll
    for (int o = 16; o > 0; o >>= 1) s += __shfl_xor_sync(0xffffffffu, s, o);
    if ((t & 31) == 0) sred[t >> 5] = s;
    __syncthreads();
    if (t < 8) {
        float w = sred[t];
        #pragma unroll
        for (int o = 4; o > 0; o >>= 1) w += __shfl_xor_sync(0xffu, w, o);
        if (t == 0) sred[0] = w;
    }
    __syncthreads();
    float inv = 1.0f / sred[0];
    v.x = ex * inv; v.y = ey * inv; v.z = ez * inv; v.w = ew * inv;
    *(float4*)(row + (t << 2)) = v;
}

// ---------------------------------------------------------------------------
// Stage 7: d_out += attn @ source_seq_out (batched NN, M=1023, N=512, K=1024;
// ping-pong)
// ---------------------------------------------------------------------------
__global__ __launch_bounds__(256, 2) void k_attns(
    const float* __restrict__ sso, float* __restrict__ out)
{
    __shared__ float As[2][BKK][128];
    __shared__ float Bs[2][BKK][128];
    int bb = blockIdx.z;
    int bm = blockIdx.x * 128, bn = blockIdx.y * 128;
    int tid = threadIdx.x;
    int tx8 = (tid & 15) << 3, ty8 = (tid >> 4) << 3;
    int rA = tid >> 1, kbA = (tid & 1) << 3;        // A loader (NT, transpose)
    int krB = tid >> 4, n0B = (tid & 15) << 3;      // B loader (NN, direct)

    int arowi = bm + rA;
    bool valid = arowi < LL;
    const float* arow = valid ? g_scores + (size_t)(bb * LL + arowi) * SS : nullptr;
    const float* bbase = sso + (size_t)bb * SS * H2;

    u64t acc[8][4] = {};
    float4 a0, a1, b0, b1;
    a0 = ldg4z(arow ? arow + kbA : nullptr);
    a1 = ldg4z(arow ? arow + kbA + 4 : nullptr);
    b0 = *(const float4*)(bbase + (size_t)krB * H2 + bn + n0B);
    b1 = *(const float4*)(bbase + (size_t)krB * H2 + bn + n0B + 4);
    sts_kmajor(As[0], rA, kbA, a0, a1);
    *(float4*)&Bs[0][krB][n0B] = b0;
    *(float4*)&Bs[0][krB][n0B + 4] = b1;
    __syncthreads();

    int p = 0;
    for (int k0 = 0; k0 < SS; k0 += BKK) {
        int kn = k0 + BKK;
        if (kn < SS) {
            a0 = ldg4z(arow ? arow + kn + kbA : nullptr);
            a1 = ldg4z(arow ? arow + kn + kbA + 4 : nullptr);
            b0 = *(const float4*)(bbase + (size_t)(kn + krB) * H2 + bn + n0B);
            b1 = *(const float4*)(bbase + (size_t)(kn + krB) * H2 + bn + n0B + 4);
        }
        micro_compute(As[p], Bs[p], acc, ty8, tx8);
        if (kn < SS) {
            sts_kmajor(As[p ^ 1], rA, kbA, a0, a1);
            *(float4*)&Bs[p ^ 1][krB][n0B] = b0;
            *(float4*)&Bs[p ^ 1][krB][n0B + 4] = b1;
            __syncthreads();
        }
        p ^= 1;
    }
    #pragma unroll
    for (int i = 0; i < 8; i++) {
        int row = bm + ty8 + i;
        if (row >= LL) continue;
        #pragma unroll
        for (int j2 = 0; j2 < 4; j2++) {
            float2 v = unpack2(acc[i][j2]);
            int col = bn + tx8 + (j2 << 1);
            out[(size_t)(bb * LL + row) * H2 + col + 0] += v.x;
            out[(size_t)(bb * LL + row) * H2 + col + 1] += v.y;
        }
    }
}

// ---------------------------------------------------------------------------
extern "C" void kernel_launch(void* const* d_in, const int* in_sizes, int n_in,
                              void* d_out, int out_size)
{
    // metadata order: source, target, enc_attn, source_seq_out, emb,
    //                 affine_w, affine_b, conv_w, conv_b, map_w, map_b
    const int*   target = (const int*)  d_in[1];
    const float* enc    = (const float*)d_in[2];
    const float* sso    = (const float*)d_in[3];
    const float* emb    = (const float*)d_in[4];
    const float* aw     = (const float*)d_in[5];
    const float* ab     = (const float*)d_in[6];
    const float* cw     = (const float*)d_in[7];
    const float* cb     = (const float*)d_in[8];
    const float* mw     = (const float*)d_in[9];
    const float* mb     = (const float*)d_in[10];
    float* out = (float*)d_out;

    k_prep_C<<<dim3(12, 2), 256>>>(cw, aw);          // fused weights (3,512,256)
    k_prep_bias<<<6, 256>>>(cw, ab);                 // fused affine bias
    k_conv_emb<<<dim3(256, 4), 256>>>(target, emb, cb);  // (B,L,2H)
    k_gate<<<MCV, 256>>>();                          // (B,L,H)
    k_dec2<<<dim3(256, 4), 256>>>(mw, mb, out);      // writes d_out
    k_scores<<<dim3(8, 8, NB), 256>>>(enc);          // (B,L,S)
    k_softmax_s<<<MCV, 256>>>();
    k_attns<<<dim3(8, 4, NB), 256>>>(sso, out);      // += into d_out
}